// round 6
// baseline (speedup 1.0000x reference)
#include <cuda_runtime.h>
#include <cuda_bf16.h>
#include <math.h>

// Lowpass EMA scan, warp-per-chain formulation.
// level_t = s*level_{t-1} + c*x_t, s = sigmoid(sm[u]), c = 1-s.
// Constant-coefficient => Kogge-Stone shuffle scan over 32 t per warp-step
// with multipliers s^1,s^2,s^4,s^8,s^16. Carry-in: + s^{lane+1}*L0.
//
// Block = 1024 threads (32 warps) owns (b, u0..u0+31), iterates T in 32-t
// tiles. Loads/stores are coalesced via smem transpose (stride-33 padding);
// 4-stage cp.async input ring + double-buffered output tile.
// 16384 warps total -> ~64 resident warps/SM (vs 3.46 for thread-per-chain),
// removing the per-warp MLP cap that pinned BW at ~4.1 TB/s.

#define LP_B 16
#define LP_T 2048
#define LP_U 1024
#define TS   32              // t per tile
#define NIT  (LP_T / TS)     // 64
#define PAD  33              // stride in floats (bank-conflict-free columns)

__device__ __forceinline__ void cp_async4(void* smem_dst, const void* gsrc) {
    unsigned sdst = (unsigned)__cvta_generic_to_shared(smem_dst);
    asm volatile("cp.async.ca.shared.global [%0], [%1], 4;\n" :: "r"(sdst), "l"(gsrc));
}
__device__ __forceinline__ void cp_async_commit() {
    asm volatile("cp.async.commit_group;\n" ::: "memory");
}
template <int N>
__device__ __forceinline__ void cp_async_wait() {
    asm volatile("cp.async.wait_group %0;\n" :: "n"(N) : "memory");
}

__global__ void __launch_bounds__(1024, 2)
lowpass_warpscan_kernel(const float* __restrict__ x,
                        const float* __restrict__ level_var,
                        const float* __restrict__ smoothing_var,
                        float* __restrict__ out)
{
    __shared__ float in_s[4][TS][PAD];   // input ring:  [stage][t_local][u_local]
    __shared__ float out_s[2][TS][PAD];  // output ping-pong

    const int w = threadIdx.x >> 5;      // warp id 0..31  (= t_local on ld/st, u_local on scan)
    const int l = threadIdx.x & 31;      // lane id        (= u_local on ld/st, t_local on scan)
    const int b  = blockIdx.x >> 5;      // 0..15
    const int u0 = (blockIdx.x & 31) * 32;

    // Per-warp chain constants (chain u = u0 + w)
    const float sv = smoothing_var[u0 + w];
    const float s  = 1.0f / (1.0f + expf(-sv));
    const float c  = 1.0f - s;
    const float s1 = s;
    const float s2 = s1 * s1;
    const float s4 = s2 * s2;
    const float s8 = s4 * s4;
    const float s16 = s8 * s8;
    const float spl = powf(s, (float)(l + 1));   // s^{lane+1}
    float L0 = level_var[u0 + w];                // carry (uniform across lanes)

    const float* __restrict__ xb = x   + (size_t)b * LP_T * LP_U;
    float*       __restrict__ ob = out + (size_t)b * LP_T * LP_U;

    // Prologue: tiles 0,1,2 in flight
#pragma unroll
    for (int p = 0; p < 3; p++) {
        cp_async4(&in_s[p][w][l], xb + (size_t)(p * TS + w) * LP_U + u0 + l);
        cp_async_commit();
    }

    for (int it = 0; it < NIT; it++) {
        // Issue tile it+3 (wraps at the end: harmless reload, never consumed,
        // keeps commit-group count uniform so wait_group<3> is always right).
        {
            const int lt = (it + 3) & (NIT - 1);
            cp_async4(&in_s[(it + 3) & 3][w][l],
                      xb + (size_t)(lt * TS + w) * LP_U + u0 + l);
            cp_async_commit();
        }
        cp_async_wait<3>();          // tile 'it' complete
        __syncthreads();

        // Scan phase: warp w owns chain u0+w; lane l holds t_local = l.
        float y = c * in_s[it & 3][l][w];

        float t1 = __shfl_up_sync(0xffffffffu, y, 1);
        if (l >= 1)  y = fmaf(s1,  t1, y);
        float t2 = __shfl_up_sync(0xffffffffu, y, 2);
        if (l >= 2)  y = fmaf(s2,  t2, y);
        float t4 = __shfl_up_sync(0xffffffffu, y, 4);
        if (l >= 4)  y = fmaf(s4,  t4, y);
        float t8 = __shfl_up_sync(0xffffffffu, y, 8);
        if (l >= 8)  y = fmaf(s8,  t8, y);
        float t16 = __shfl_up_sync(0xffffffffu, y, 16);
        if (l >= 16) y = fmaf(s16, t16, y);

        const float level = fmaf(spl, L0, y);     // + s^{l+1} * carry
        L0 = __shfl_sync(0xffffffffu, level, 31); // carry-out

        out_s[it & 1][l][w] = level;              // transpose back
        __syncthreads();

        // Store phase: warp w writes row t_local = w, coalesced.
        ob[(size_t)(it * TS + w) * LP_U + u0 + l] = out_s[it & 1][w][l];
    }

    cp_async_wait<0>();   // drain the harmless wrap loads before exit
}

extern "C" void kernel_launch(void* const* d_in, const int* in_sizes, int n_in,
                              void* d_out, int out_size)
{
    const float* x         = (const float*)d_in[0];  // [B,T,U]
    const float* level_var = (const float*)d_in[1];  // [1,U]
    const float* smoothing = (const float*)d_in[2];  // [1,U]
    float* out             = (float*)d_out;          // [B,T,U]

    const int blocks = LP_B * (LP_U / 32);           // 512
    lowpass_warpscan_kernel<<<blocks, 1024>>>(x, level_var, smoothing, out);
}

// round 7
// speedup vs baseline: 1.8561x; 1.8561x over previous
#include <cuda_runtime.h>
#include <cuda_bf16.h>
#include <math.h>

// Lowpass EMA scan: out[b,t,u] = (1-s[u])*x[b,t,u] + s[u]*prev
// Thread-per-chain (carry in register, 2 ops/element) with cp.async-staged
// input tiles. LDGSTS has no per-warp outstanding cap (unlike LDG's ~55
// scoreboard limit that pinned R5 at 4.1 TB/s), so a 5-stage ring with 3
// tiles in flight gives ~96KB/SM of reads outstanding -> HBM saturation.
//
// Block = 128 threads = chains (b, u0..u0+127); grid = 128 blocks.
// Tile = 64 t-rows x 512B (32KB). Loads: 16B cp.async.cg, coalesced.
// Consume: LDS (conflict-free) + FMA + coalesced STG per element.

#define LP_B   16
#define LP_T   2048
#define LP_U   1024
#define TPB    128           // threads = chains per block
#define TT     64            // t per tile
#define NIT    (LP_T / TT)   // 32
#define RING   5
#define STAGE_FLOATS (TT * TPB)                 // 8192 floats = 32KB
#define SMEM_BYTES   (RING * STAGE_FLOATS * 4)  // 160KB

__device__ __forceinline__ void cp_async16(float* smem_dst, const float* gsrc) {
    unsigned sdst = (unsigned)__cvta_generic_to_shared(smem_dst);
    asm volatile("cp.async.cg.shared.global [%0], [%1], 16;\n"
                 :: "r"(sdst), "l"(gsrc));
}
__device__ __forceinline__ void cp_async_commit() {
    asm volatile("cp.async.commit_group;\n" ::: "memory");
}
template <int N>
__device__ __forceinline__ void cp_async_wait() {
    asm volatile("cp.async.wait_group %0;\n" :: "n"(N) : "memory");
}

__global__ void __launch_bounds__(TPB, 1)
lowpass_cpasync_kernel(const float* __restrict__ x,
                       const float* __restrict__ level_var,
                       const float* __restrict__ smoothing_var,
                       float* __restrict__ out)
{
    extern __shared__ float xs[];   // [RING][TT][TPB]

    const int tid = threadIdx.x;
    const int b   = blockIdx.x >> 3;          // 0..15
    const int u0  = (blockIdx.x & 7) << 7;    // 0,128,...,896
    const int u   = u0 + tid;

    const float sv = smoothing_var[u];
    const float s  = 1.0f / (1.0f + expf(-sv));
    const float c  = 1.0f - s;
    float level    = level_var[u];

    const float* __restrict__ xb = x   + (size_t)b * LP_T * LP_U;
    float*       __restrict__ ob = out + (size_t)b * LP_T * LP_U;

    // Load mapping: thread covers rows (tid>>5)+4k, 16B at float col (tid&31)*4
    const int lrow = tid >> 5;          // 0..3
    const int lcol = (tid & 31) << 2;   // 0,4,...,124

    // Prologue: tiles 0,1,2 in flight
#pragma unroll
    for (int p = 0; p < 3; p++) {
        float* st = xs + p * STAGE_FLOATS;
#pragma unroll
        for (int k = 0; k < 16; k++) {
            const int r = lrow + 4 * k;
            cp_async16(st + r * TPB + lcol,
                       xb + (size_t)(p * TT + r) * LP_U + u0 + lcol);
        }
        cp_async_commit();
    }

    for (int it = 0; it < NIT; it++) {
        cp_async_wait<2>();     // tile 'it' has landed
        __syncthreads();        // all threads' slices visible; prior slot free

        // Issue tile it+3 into slot (it+3)%RING (consumed 2 iters ago -> safe)
        const int ls = it + 3;
        if (ls < NIT) {
            float* st = xs + (ls % RING) * STAGE_FLOATS;
#pragma unroll
            for (int k = 0; k < 16; k++) {
                const int r = lrow + 4 * k;
                cp_async16(st + r * TPB + lcol,
                           xb + (size_t)(ls * TT + r) * LP_U + u0 + lcol);
            }
        }
        cp_async_commit();      // empty group near the end keeps counts uniform

        // Consume tile it: serial carry, coalesced stores
        const float* tile = xs + (it % RING) * STAGE_FLOATS;
        float* op = ob + (size_t)(it * TT) * LP_U + u;
#pragma unroll
        for (int t = 0; t < TT; t++) {
            level = fmaf(s, level, c * tile[t * TPB + tid]);
            __stcs(op + (size_t)t * LP_U, level);
        }
    }
}

extern "C" void kernel_launch(void* const* d_in, const int* in_sizes, int n_in,
                              void* d_out, int out_size)
{
    const float* x         = (const float*)d_in[0];  // [B,T,U]
    const float* level_var = (const float*)d_in[1];  // [1,U]
    const float* smoothing = (const float*)d_in[2];  // [1,U]
    float* out             = (float*)d_out;          // [B,T,U]

    static int smem_set = 0;
    if (!smem_set) {
        cudaFuncSetAttribute(lowpass_cpasync_kernel,
                             cudaFuncAttributeMaxDynamicSharedMemorySize,
                             SMEM_BYTES);
        smem_set = 1;
    }

    const int blocks = LP_B * (LP_U / TPB);          // 128
    lowpass_cpasync_kernel<<<blocks, TPB, SMEM_BYTES>>>(x, level_var, smoothing, out);
}

// round 8
// speedup vs baseline: 1.8737x; 1.0095x over previous
#include <cuda_runtime.h>
#include <cuda_bf16.h>
#include <math.h>

// Lowpass EMA scan: out[b,t,u] = (1-s[u])*x[b,t,u] + s[u]*prev
// Thread-per-chain (carry in register) + cp.async-staged input tiles.
// R8: 6-stage ring, 4-tile prologue, next-tile issue hoisted ABOVE the
// wait (slot reuse protected by the barrier two iterations back), so
// steady state holds ~5 tiles (160KB/SM) of reads in flight and the LSU
// never idles during wait windows.
//
// Block = 128 threads = chains (b, u0..u0+127); grid = 128 blocks.
// Tile = 64 t-rows x 512B (32KB). Loads: 16B cp.async.cg, coalesced.

#define LP_B   16
#define LP_T   2048
#define LP_U   1024
#define TPB    128           // threads = chains per block
#define TT     64            // t per tile
#define NIT    (LP_T / TT)   // 32
#define RING   6
#define STAGE_FLOATS (TT * TPB)                 // 8192 floats = 32KB
#define SMEM_BYTES   (RING * STAGE_FLOATS * 4)  // 192KB

__device__ __forceinline__ void cp_async16(float* smem_dst, const float* gsrc) {
    unsigned sdst = (unsigned)__cvta_generic_to_shared(smem_dst);
    asm volatile("cp.async.cg.shared.global [%0], [%1], 16;\n"
                 :: "r"(sdst), "l"(gsrc));
}
__device__ __forceinline__ void cp_async_commit() {
    asm volatile("cp.async.commit_group;\n" ::: "memory");
}
template <int N>
__device__ __forceinline__ void cp_async_wait() {
    asm volatile("cp.async.wait_group %0;\n" :: "n"(N) : "memory");
}

__global__ void __launch_bounds__(TPB, 1)
lowpass_cpasync_kernel(const float* __restrict__ x,
                       const float* __restrict__ level_var,
                       const float* __restrict__ smoothing_var,
                       float* __restrict__ out)
{
    extern __shared__ float xs[];   // [RING][TT][TPB]

    const int tid = threadIdx.x;
    const int b   = blockIdx.x >> 3;          // 0..15
    const int u0  = (blockIdx.x & 7) << 7;    // 0,128,...,896
    const int u   = u0 + tid;

    const float sv = smoothing_var[u];
    const float s  = 1.0f / (1.0f + expf(-sv));
    const float c  = 1.0f - s;
    float level    = level_var[u];

    const float* __restrict__ xb = x   + (size_t)b * LP_T * LP_U;
    float*       __restrict__ ob = out + (size_t)b * LP_T * LP_U;

    // Load mapping: thread covers rows (tid>>5)+4k, 16B at float col (tid&31)*4
    const int lrow = tid >> 5;          // 0..3
    const int lcol = (tid & 31) << 2;   // 0,4,...,124

    // Prologue: tiles 0..3 in flight (4 groups)
#pragma unroll
    for (int p = 0; p < 4; p++) {
        float* st = xs + p * STAGE_FLOATS;
#pragma unroll
        for (int k = 0; k < 16; k++) {
            const int r = lrow + 4 * k;
            cp_async16(st + r * TPB + lcol,
                       xb + (size_t)(p * TT + r) * LP_U + u0 + lcol);
        }
        cp_async_commit();
    }

    for (int it = 0; it < NIT; it++) {
        // Issue tile it+4 FIRST (slot (it+4)%RING held tile it-2, whose
        // consumption by all warps is fenced by the barrier at it-1).
        const int ls = it + 4;
        if (ls < NIT) {
            float* st = xs + (ls % RING) * STAGE_FLOATS;
#pragma unroll
            for (int k = 0; k < 16; k++) {
                const int r = lrow + 4 * k;
                cp_async16(st + r * TPB + lcol,
                           xb + (size_t)(ls * TT + r) * LP_U + u0 + lcol);
            }
        }
        cp_async_commit();      // empty groups near the end keep counts uniform

        cp_async_wait<4>();     // <=4 of 5 pending -> tile 'it' has landed
        __syncthreads();        // all threads' slices visible; old slot free

        // Consume tile it: serial carry, coalesced stores
        const float* tile = xs + (it % RING) * STAGE_FLOATS;
        float* op = ob + (size_t)(it * TT) * LP_U + u;
#pragma unroll
        for (int t = 0; t < TT; t++) {
            level = fmaf(s, level, c * tile[t * TPB + tid]);
            __stcs(op + (size_t)t * LP_U, level);
        }
    }
}

extern "C" void kernel_launch(void* const* d_in, const int* in_sizes, int n_in,
                              void* d_out, int out_size)
{
    const float* x         = (const float*)d_in[0];  // [B,T,U]
    const float* level_var = (const float*)d_in[1];  // [1,U]
    const float* smoothing = (const float*)d_in[2];  // [1,U]
    float* out             = (float*)d_out;          // [B,T,U]

    static int smem_set = 0;
    if (!smem_set) {
        cudaFuncSetAttribute(lowpass_cpasync_kernel,
                             cudaFuncAttributeMaxDynamicSharedMemorySize,
                             SMEM_BYTES);
        smem_set = 1;
    }

    const int blocks = LP_B * (LP_U / TPB);          // 128
    lowpass_cpasync_kernel<<<blocks, TPB, SMEM_BYTES>>>(x, level_var, smoothing, out);
}